// round 12
// baseline (speedup 1.0000x reference)
#include <cuda_runtime.h>
#include <cuda_fp16.h>
#include <cstdint>
#include <math.h>

// Problem shape (fixed): B=8, T=2048, C=1024
constexpr int kB = 8;
constexpr int kT = 2048;
constexpr int kC = 1024;
constexpr int kM = kB * kT;                 // 16384 rows
constexpr size_t kMC = (size_t)kM * kC;
constexpr size_t kCC = (size_t)kC * kC;

constexpr int kSeg    = 16;
constexpr int kSegLen = kT / kSeg;          // 128

// ---------------------------------------------------------------------------
// Scratch (__device__ globals)
// ---------------------------------------------------------------------------
__device__ __half g_a[3][kMC];     // mixed inputs (k,v,r) in fp16
__device__ __half g_w[4][kCC];     // wk,wv,wr,wo in fp16
__device__ float  g_k[kMC];        // key (fp32: feeds exp twice)
__device__ __half g_v16[kMC];      // value (fp16)
__device__ __half g_r16[kMC];      // sigmoid(receptance) (fp16)
__device__ __half g_rw[kMC];       // rwkv in fp16
__device__ float g_segN[(size_t)kB * kSeg * kC];
__device__ float g_segD[(size_t)kB * kSeg * kC];
__device__ float g_segM[(size_t)kB * kSeg * kC];

// phase counters: [0]=k+v tiles, [1]=r tiles, [2]=segA, [3]=prefix, [4+bs]=segB
__device__ int g_cnt[4 + kB * kSeg];

// ---------------------------------------------------------------------------
// PTX helpers
// ---------------------------------------------------------------------------
__device__ __forceinline__ uint32_t smem_u32(const void* p) {
    uint32_t a;
    asm("{ .reg .u64 t; cvta.to.shared.u64 t, %1; cvt.u32.u64 %0, t; }"
        : "=r"(a) : "l"(p));
    return a;
}
__device__ __forceinline__ void cp_async16(uint32_t saddr, const void* gptr) {
    asm volatile("cp.async.ca.shared.global [%0], [%1], 16;"
                 :: "r"(saddr), "l"(gptr));
}
__device__ __forceinline__ void cp_commit() {
    asm volatile("cp.async.commit_group;");
}
template <int N>
__device__ __forceinline__ void cp_wait() {
    asm volatile("cp.async.wait_group %0;" :: "n"(N));
}
__device__ __forceinline__ void ldsm_x4(uint32_t* r, uint32_t addr) {
    asm volatile("ldmatrix.sync.aligned.m8n8.x4.shared.b16 {%0,%1,%2,%3}, [%4];"
                 : "=r"(r[0]), "=r"(r[1]), "=r"(r[2]), "=r"(r[3]) : "r"(addr));
}
__device__ __forceinline__ void mma16816(float* d, const uint32_t* a, const uint32_t* b) {
    asm volatile("mma.sync.aligned.m16n8k16.row.col.f32.f16.f16.f32 "
                 "{%0,%1,%2,%3}, {%4,%5,%6,%7}, {%8,%9}, {%0,%1,%2,%3};"
                 : "+f"(d[0]), "+f"(d[1]), "+f"(d[2]), "+f"(d[3])
                 : "r"(a[0]), "r"(a[1]), "r"(a[2]), "r"(a[3]), "r"(b[0]), "r"(b[1]));
}

__device__ __forceinline__ void h4_store(const float* a, __half* d, size_t off) {
    unsigned short u[4];
#pragma unroll
    for (int i = 0; i < 4; i++) u[i] = __half_as_ushort(__float2half_rn(a[i]));
    *(uint2*)(d + off) = make_uint2((uint32_t)u[0] | ((uint32_t)u[1] << 16),
                                    (uint32_t)u[2] | ((uint32_t)u[3] << 16));
}

// producer: make writes visible, then bump counter
__device__ __forceinline__ void post_count(int idx) {
    __threadfence();
    __syncthreads();
    if (threadIdx.x == 0) atomicAdd(&g_cnt[idx], 1);
}
// consumer: spin until counter reaches target
__device__ __forceinline__ void wait_count(int idx, int target) {
    if (threadIdx.x == 0) {
        volatile int* p = &g_cnt[idx];
        while (*p < target) __nanosleep(128);
        __threadfence();
    }
    __syncthreads();
}

// ---------------------------------------------------------------------------
// prep: zero counters + weights + mixed inputs in ONE launch
// ---------------------------------------------------------------------------
__global__ __launch_bounds__(256) void prep_all_kernel(
    const float* __restrict__ x,
    const float* __restrict__ wk, const float* __restrict__ wv,
    const float* __restrict__ wr, const float* __restrict__ wo,
    const float* __restrict__ mk, const float* __restrict__ mv,
    const float* __restrict__ mr)
{
    const int bid = blockIdx.x;
    const int c4  = threadIdx.x;
    if (bid == 0 && c4 < 4 + kB * kSeg) g_cnt[c4] = 0;
    if (bid < 4096) {
        const int mat = bid >> 10;
        const int row = bid & 1023;
        const float* src = mat == 0 ? wk : mat == 1 ? wv : mat == 2 ? wr : wo;
        float4 v = ((const float4*)(src + (size_t)row * kC))[c4];
        h4_store((const float*)&v, g_w[mat], (size_t)row * kC + c4 * 4);
        return;
    }
    const int row = bid - 4096;
    const float4 xv = ((const float4*)(x + (size_t)row * kC))[c4];
    float4 pv = make_float4(0.f, 0.f, 0.f, 0.f);
    if ((row & (kT - 1)) != 0)
        pv = ((const float4*)(x + (size_t)(row - 1) * kC))[c4];
    const float4 m0 = ((const float4*)mk)[c4];
    const float4 m1 = ((const float4*)mv)[c4];
    const float4 m2 = ((const float4*)mr)[c4];
    const float* xe = (const float*)&xv;
    const float* pe = (const float*)&pv;
    const float* me[3] = {(const float*)&m0, (const float*)&m1, (const float*)&m2};
    const size_t off = (size_t)row * kC + c4 * 4;
#pragma unroll
    for (int s = 0; s < 3; s++) {
        float a[4];
#pragma unroll
        for (int i = 0; i < 4; i++)
            a[i] = fmaf(me[s][i], xe[i] - pe[i], pe[i]);
        h4_store(a, g_a[s], off);
    }
}

// ---------------------------------------------------------------------------
// fp16 warp-MMA GEMM body (CTA 128x128, K-chunk 64, 8 warps, dbl-buffer)
// ---------------------------------------------------------------------------
constexpr int kStrideB16 = 72;
constexpr int kRowBytes  = kStrideB16 * 2;   // 144
constexpr int kTileBytes = 128 * kRowBytes;  // 18432
constexpr int kStageBytes = 2 * kTileBytes;  // 36864
constexpr int kSmemBytes  = 2 * kStageBytes; // 73728
constexpr int OFF_A = 0;
constexpr int OFF_B = kTileBytes;

__device__ __forceinline__ void load_chunk(uint32_t sb, int stage, int tid,
                                           const __half* A, const __half* B,
                                           int m0, int n0, int k0) {
    const uint32_t st = sb + stage * kStageBytes;
    const __half* srcs[2] = {A, B};
    const int bases[2] = {m0, n0};
    const uint32_t offs[2] = {OFF_A, OFF_B};
#pragma unroll
    for (int t = 0; t < 2; t++) {
#pragma unroll
        for (int rep = 0; rep < 4; rep++) {
            const int j = tid + rep * 256;
            const int row = j >> 3;
            const int seg = j & 7;
            const __half* g = srcs[t] + (size_t)(bases[t] + row) * kC + k0 + seg * 8;
            cp_async16(st + offs[t] + row * kRowBytes + seg * 16, g);
        }
    }
}

template <typename OutT, bool SIG>
__device__ __forceinline__ void gemm_body(const __half* __restrict__ A,
                                          const __half* __restrict__ B,
                                          OutT* __restrict__ out,
                                          int m0, int n0) {
    extern __shared__ char smem[];
    const uint32_t sb = smem_u32(smem);
    const int tid  = threadIdx.x;
    const int wid  = tid >> 5;
    const int lane = tid & 31;
    const int wm   = wid & 3;
    const int wn   = wid >> 2;

    float acc[2][8][4];
#pragma unroll
    for (int mt = 0; mt < 2; mt++)
#pragma unroll
        for (int nt = 0; nt < 8; nt++)
#pragma unroll
            for (int i = 0; i < 4; i++) acc[mt][nt][i] = 0.f;

    const uint32_t aRowOff = (uint32_t)((wm * 32 + (lane & 15)) * kRowBytes + (lane >> 4) * 16);
    const uint32_t bRowOff = (uint32_t)((wn * 64 + (lane & 7) + ((lane & 16) >> 1)) * kRowBytes
                                        + ((lane >> 3) & 1) * 16);

    load_chunk(sb, 0, tid, A, B, m0, n0, 0);
    cp_commit();

    const int nChunks = kC / 64;   // 16
    for (int c = 0; c < nChunks; c++) {
        if (c + 1 < nChunks) {
            load_chunk(sb, (c + 1) & 1, tid, A, B, m0, n0, (c + 1) * 64);
            cp_commit();
            cp_wait<1>();
        } else {
            cp_wait<0>();
        }
        __syncthreads();

        const uint32_t st = sb + (c & 1) * kStageBytes;
#pragma unroll
        for (int kk = 0; kk < 4; kk++) {
            const uint32_t kOff = kk * 32;
            uint32_t ah[2][4], b[8][2];
#pragma unroll
            for (int mt = 0; mt < 2; mt++)
                ldsm_x4(ah[mt], st + OFF_A + aRowOff + mt * 16 * kRowBytes + kOff);
#pragma unroll
            for (int np = 0; np < 4; np++)
                ldsm_x4(&b[np * 2][0], st + OFF_B + bRowOff + np * 16 * kRowBytes + kOff);
#pragma unroll
            for (int mt = 0; mt < 2; mt++)
#pragma unroll
                for (int nt = 0; nt < 8; nt++)
                    mma16816(acc[mt][nt], ah[mt], b[nt]);
        }
        __syncthreads();
    }

    const int mBase = m0 + wm * 32;
    const int nBase = n0 + wn * 64;
#pragma unroll
    for (int mt = 0; mt < 2; mt++) {
#pragma unroll
        for (int nt = 0; nt < 8; nt++) {
            float* a4 = acc[mt][nt];
            if (SIG) {
#pragma unroll
                for (int i = 0; i < 4; i++)
                    a4[i] = 1.f / (1.f + __expf(-a4[i]));
            }
            const int r0 = mBase + mt * 16 + (lane >> 2);
            const int cc = nBase + nt * 8 + (lane & 3) * 2;
            if constexpr (sizeof(OutT) == 4) {
                *(float2*)((float*)out + (size_t)r0 * kC + cc)       = make_float2(a4[0], a4[1]);
                *(float2*)((float*)out + (size_t)(r0 + 8) * kC + cc) = make_float2(a4[2], a4[3]);
            } else {
                *(__half2*)((__half*)out + (size_t)r0 * kC + cc)       = __floats2half2_rn(a4[0], a4[1]);
                *(__half2*)((__half*)out + (size_t)(r0 + 8) * kC + cc) = __floats2half2_rn(a4[2], a4[3]);
            }
        }
    }
}

// ---------------------------------------------------------------------------
// wkv phase bodies (one-exp formulation)
// ---------------------------------------------------------------------------
__device__ void segA_body(int local, const float* __restrict__ td) {
    const int tid = threadIdx.x;
    const int cblk = local & 3;
    const int bs   = local >> 2;               // 0..127  (b*kSeg + seg)
    const int c = cblk * 256 + tid;
    const int b  = bs >> 4;
    const int sg = bs & (kSeg - 1);

    const float w = -__expf(td[c]);
    const size_t base = ((size_t)b * kT + (size_t)sg * kSegLen) * kC + c;
    const float*  kp = g_k   + base;
    const __half* vp = g_v16 + base;

    float num = 0.f, den = 0.f, mx = -1e38f;
#pragma unroll 4
    for (int i = 0; i < kSegLen; i++) {
        const float k = kp[(size_t)i * kC];
        const float v = __half2float(vp[(size_t)i * kC]);
        const float mw = mx + w;
        const float d  = mw - k;
        const bool  p  = d >= 0.f;
        const float e  = __expf(p ? -d : d);
        const float f1 = p ? 1.f : e;
        const float f2 = p ? e : 1.f;
        num = fmaf(f1, num, f2 * v);
        den = fmaf(f1, den, f2);
        mx  = p ? mw : k;
    }
    const size_t si = (size_t)bs * kC + c;
    g_segN[si] = num;
    g_segD[si] = den;
    g_segM[si] = mx;
}

__device__ void prefix_body(int local, const float* __restrict__ td) {
    const int idx = local * 256 + threadIdx.x;   // 0..8191
    const int b = idx >> 10;
    const int c = idx & (kC - 1);
    const float w = -__expf(td[c]);
    const float shift = (float)kSegLen * w;

    float n[kSeg], d[kSeg], m[kSeg];
#pragma unroll
    for (int s = 0; s < kSeg; s++) {
        const size_t si = ((size_t)(b * kSeg + s)) * kC + c;
        n[s] = g_segN[si];
        d[s] = g_segD[si];
        m[s] = g_segM[si];
    }
    float N = 0.f, D = 0.f, M = -1e38f;
#pragma unroll
    for (int s = 0; s < kSeg; s++) {
        const size_t si = ((size_t)(b * kSeg + s)) * kC + c;
        g_segN[si] = N;
        g_segD[si] = D;
        g_segM[si] = M;
        const float Ms = M + shift;
        const float dd = Ms - m[s];
        const bool  p  = dd >= 0.f;
        const float e  = __expf(p ? -dd : dd);
        const float f1 = p ? 1.f : e;
        const float f2 = p ? e : 1.f;
        N = fmaf(f1, N, f2 * n[s]);
        D = fmaf(f1, D, f2 * d[s]);
        M = p ? Ms : m[s];
    }
}

__device__ void segB_body(int local, const float* __restrict__ td,
                          const float* __restrict__ tf) {
    const int tid = threadIdx.x;
    const int cblk = local & 3;
    const int bs   = local >> 2;
    const int c = cblk * 256 + tid;
    const int b  = bs >> 4;
    const int sg = bs & (kSeg - 1);

    const float w = -__expf(td[c]);
    const float u = tf[c];

    const size_t si = (size_t)bs * kC + c;
    float num = g_segN[si];
    float den = g_segD[si];
    float mx  = g_segM[si];

    const size_t base = ((size_t)b * kT + (size_t)sg * kSegLen) * kC + c;
    const float*  kp = g_k   + base;
    const __half* vp = g_v16 + base;
    const __half* rp = g_r16 + base;
    __half* op = g_rw + base;

#pragma unroll 4
    for (int i = 0; i < kSegLen; i++) {
        const size_t o = (size_t)i * kC;
        const float k = kp[o];
        const float v = __half2float(vp[o]);
        const float r = __half2float(rp[o]);
        const float ku  = k + u;
        const float do_ = mx - ku;
        const bool  po  = do_ >= 0.f;
        const float eo  = __expf(po ? -do_ : do_);
        const float g1  = po ? 1.f : eo;
        const float g2  = po ? eo : 1.f;
        const float outv = __fdividef(fmaf(g1, num, g2 * v), fmaf(g1, den, g2));
        const float mw = mx + w;
        const float d  = mw - k;
        const bool  p  = d >= 0.f;
        const float e  = __expf(p ? -d : d);
        const float f1 = p ? 1.f : e;
        const float f2 = p ? e : 1.f;
        num = fmaf(f1, num, f2 * v);
        den = fmaf(f1, den, f2);
        mx  = p ? mw : k;

        op[o] = __float2half_rn(r * outv);
    }
}

// ---------------------------------------------------------------------------
// MEGA kernel: phases ordered by blockIdx; counter-gated dependencies.
// [0,2048)   k,v GEMM tiles            -> cnt[0]
// [2048,3072) r GEMM tiles             -> cnt[1]
// [3072,3584) segA  (wait cnt[0]==2048) -> cnt[2]
// [3584,3616) prefix (wait cnt[2]==512) -> cnt[3]
// [3616,4128) segB  (wait cnt[3]==32 && cnt[1]==1024) -> cnt[4+bs]
// [4128,5152) out GEMM (wait cnt[4+mt]==4)
// ---------------------------------------------------------------------------
__global__ __launch_bounds__(256, 2) void mega_kernel(
    const float* __restrict__ td, const float* __restrict__ tf,
    float* __restrict__ out)
{
    const int bid = blockIdx.x;
    if (bid < 3072) {
        const int z = bid >> 10;
        const int t = bid & 1023;
        const int m0 = (t >> 3) * 128;
        const int n0 = (t & 7) * 128;
        if (z == 0) {
            gemm_body<float, false>(g_a[0], g_w[0], g_k, m0, n0);
            post_count(0);
        } else if (z == 1) {
            gemm_body<__half, false>(g_a[1], g_w[1], g_v16, m0, n0);
            post_count(0);
        } else {
            gemm_body<__half, true>(g_a[2], g_w[2], g_r16, m0, n0);
            post_count(1);
        }
        return;
    }
    if (bid < 3584) {
        wait_count(0, 2048);
        segA_body(bid - 3072, td);
        post_count(2);
        return;
    }
    if (bid < 3616) {
        wait_count(2, 512);
        prefix_body(bid - 3584, td);
        post_count(3);
        return;
    }
    if (bid < 4128) {
        const int local = bid - 3616;
        wait_count(3, 32);
        wait_count(1, 1024);
        segB_body(local, td, tf);
        post_count(4 + (local >> 2));
        return;
    }
    {
        const int local = bid - 4128;
        const int mt = local >> 3;
        wait_count(4 + mt, 4);
        gemm_body<float, false>(g_rw, g_w[3], out, mt * 128, (local & 7) * 128);
    }
}

// ---------------------------------------------------------------------------
// Launch
// ---------------------------------------------------------------------------
extern "C" void kernel_launch(void* const* d_in, const int* in_sizes, int n_in,
                              void* d_out, int out_size) {
    const float* x  = (const float*)d_in[0];
    const float* wk = (const float*)d_in[1];
    const float* wv = (const float*)d_in[2];
    const float* wr = (const float*)d_in[3];
    const float* wo = (const float*)d_in[4];
    const float* td = (const float*)d_in[5];
    const float* tf = (const float*)d_in[6];
    const float* mk = (const float*)d_in[7];
    const float* mv = (const float*)d_in[8];
    const float* mr = (const float*)d_in[9];
    float* out = (float*)d_out;

    cudaFuncSetAttribute(mega_kernel, cudaFuncAttributeMaxDynamicSharedMemorySize, kSmemBytes);

    prep_all_kernel<<<4096 + kM, 256>>>(x, wk, wv, wr, wo, mk, mv, mr);
    mega_kernel<<<5152, 256, kSmemBytes>>>(td, tf, out);
}

// round 13
// speedup vs baseline: 1.0956x; 1.0956x over previous
#include <cuda_runtime.h>
#include <cuda_fp16.h>
#include <cstdint>
#include <math.h>

// Problem shape (fixed): B=8, T=2048, C=1024
constexpr int kB = 8;
constexpr int kT = 2048;
constexpr int kC = 1024;
constexpr int kM = kB * kT;                 // 16384 rows
constexpr size_t kMC = (size_t)kM * kC;
constexpr size_t kCC = (size_t)kC * kC;

constexpr int kSeg    = 16;
constexpr int kSegLen = kT / kSeg;          // 128

// ---------------------------------------------------------------------------
// Scratch (__device__ globals)
// ---------------------------------------------------------------------------
__device__ __half g_a[3][kMC];     // mixed inputs (k,v,r) in fp16
__device__ __half g_w[4][kCC];     // wk,wv,wr,wo in fp16
__device__ float  g_k[kMC];        // key (fp32: feeds exp twice)
__device__ __half g_v16[kMC];      // value (fp16)
__device__ __half g_r16[kMC];      // sigmoid(receptance) (fp16)
__device__ __half g_rw[kMC];       // rwkv in fp16
__device__ float g_segN[(size_t)kB * kSeg * kC];
__device__ float g_segD[(size_t)kB * kSeg * kC];
__device__ float g_segM[(size_t)kB * kSeg * kC];

// ---------------------------------------------------------------------------
// PTX helpers
// ---------------------------------------------------------------------------
__device__ __forceinline__ uint32_t smem_u32(const void* p) {
    uint32_t a;
    asm("{ .reg .u64 t; cvta.to.shared.u64 t, %1; cvt.u32.u64 %0, t; }"
        : "=r"(a) : "l"(p));
    return a;
}
__device__ __forceinline__ void cp_async16(uint32_t saddr, const void* gptr) {
    asm volatile("cp.async.ca.shared.global [%0], [%1], 16;"
                 :: "r"(saddr), "l"(gptr));
}
__device__ __forceinline__ void cp_commit() {
    asm volatile("cp.async.commit_group;");
}
template <int N>
__device__ __forceinline__ void cp_wait() {
    asm volatile("cp.async.wait_group %0;" :: "n"(N));
}
__device__ __forceinline__ void ldsm_x4(uint32_t* r, uint32_t addr) {
    asm volatile("ldmatrix.sync.aligned.m8n8.x4.shared.b16 {%0,%1,%2,%3}, [%4];"
                 : "=r"(r[0]), "=r"(r[1]), "=r"(r[2]), "=r"(r[3]) : "r"(addr));
}
__device__ __forceinline__ void mma16816(float* d, const uint32_t* a, const uint32_t* b) {
    asm volatile("mma.sync.aligned.m16n8k16.row.col.f32.f16.f16.f32 "
                 "{%0,%1,%2,%3}, {%4,%5,%6,%7}, {%8,%9}, {%0,%1,%2,%3};"
                 : "+f"(d[0]), "+f"(d[1]), "+f"(d[2]), "+f"(d[3])
                 : "r"(a[0]), "r"(a[1]), "r"(a[2]), "r"(a[3]), "r"(b[0]), "r"(b[1]));
}

__device__ __forceinline__ void h4_store(const float* a, __half* d, size_t off) {
    unsigned short u[4];
#pragma unroll
    for (int i = 0; i < 4; i++) u[i] = __half_as_ushort(__float2half_rn(a[i]));
    *(uint2*)(d + off) = make_uint2((uint32_t)u[0] | ((uint32_t)u[1] << 16),
                                    (uint32_t)u[2] | ((uint32_t)u[3] << 16));
}

// ---------------------------------------------------------------------------
// prep: weights + mixed inputs in ONE launch
// ---------------------------------------------------------------------------
__global__ __launch_bounds__(256) void prep_all_kernel(
    const float* __restrict__ x,
    const float* __restrict__ wk, const float* __restrict__ wv,
    const float* __restrict__ wr, const float* __restrict__ wo,
    const float* __restrict__ mk, const float* __restrict__ mv,
    const float* __restrict__ mr)
{
    const int bid = blockIdx.x;
    const int c4  = threadIdx.x;
    if (bid < 4096) {
        const int mat = bid >> 10;
        const int row = bid & 1023;
        const float* src = mat == 0 ? wk : mat == 1 ? wv : mat == 2 ? wr : wo;
        float4 v = ((const float4*)(src + (size_t)row * kC))[c4];
        h4_store((const float*)&v, g_w[mat], (size_t)row * kC + c4 * 4);
        return;
    }
    const int row = bid - 4096;
    const float4 xv = ((const float4*)(x + (size_t)row * kC))[c4];
    float4 pv = make_float4(0.f, 0.f, 0.f, 0.f);
    if ((row & (kT - 1)) != 0)
        pv = ((const float4*)(x + (size_t)(row - 1) * kC))[c4];
    const float4 m0 = ((const float4*)mk)[c4];
    const float4 m1 = ((const float4*)mv)[c4];
    const float4 m2 = ((const float4*)mr)[c4];
    const float* xe = (const float*)&xv;
    const float* pe = (const float*)&pv;
    const float* me[3] = {(const float*)&m0, (const float*)&m1, (const float*)&m2};
    const size_t off = (size_t)row * kC + c4 * 4;
#pragma unroll
    for (int s = 0; s < 3; s++) {
        float a[4];
#pragma unroll
        for (int i = 0; i < 4; i++)
            a[i] = fmaf(me[s][i], xe[i] - pe[i], pe[i]);
        h4_store(a, g_a[s], off);
    }
}

// ---------------------------------------------------------------------------
// fp16 warp-MMA GEMM: CTA 128x128, 4 warps (128 thr), warp tile 64x64,
// K-chunk 64, cp.async double-buffer.
// ---------------------------------------------------------------------------
constexpr int kStrideB16 = 72;
constexpr int kRowBytes  = kStrideB16 * 2;   // 144
constexpr int kTileBytes = 128 * kRowBytes;  // 18432
constexpr int kStageBytes = 2 * kTileBytes;  // 36864
constexpr int kSmemBytes  = 2 * kStageBytes; // 73728
constexpr int OFF_A = 0;
constexpr int OFF_B = kTileBytes;

__device__ __forceinline__ void load_chunk(uint32_t sb, int stage, int tid,
                                           const __half* A, const __half* B,
                                           int m0, int n0, int k0) {
    const uint32_t st = sb + stage * kStageBytes;
    const __half* srcs[2] = {A, B};
    const int bases[2] = {m0, n0};
    const uint32_t offs[2] = {OFF_A, OFF_B};
#pragma unroll
    for (int t = 0; t < 2; t++) {
#pragma unroll
        for (int rep = 0; rep < 8; rep++) {
            const int j = tid + rep * 128;         // 0..1023
            const int row = j >> 3;
            const int seg = j & 7;
            const __half* g = srcs[t] + (size_t)(bases[t] + row) * kC + k0 + seg * 8;
            cp_async16(st + offs[t] + row * kRowBytes + seg * 16, g);
        }
    }
}

template <typename OutT, bool SIG>
__device__ __forceinline__ void gemm_body(const __half* __restrict__ A,
                                          const __half* __restrict__ B,
                                          OutT* __restrict__ out,
                                          int m0, int n0) {
    extern __shared__ char smem[];
    const uint32_t sb = smem_u32(smem);
    const int tid  = threadIdx.x;
    const int wid  = tid >> 5;
    const int lane = tid & 31;
    const int wm   = wid & 1;        // m offset wm*64
    const int wn   = wid >> 1;       // n offset wn*64

    float acc[4][8][4];
#pragma unroll
    for (int mt = 0; mt < 4; mt++)
#pragma unroll
        for (int nt = 0; nt < 8; nt++)
#pragma unroll
            for (int i = 0; i < 4; i++) acc[mt][nt][i] = 0.f;

    const uint32_t aRowOff = (uint32_t)((wm * 64 + (lane & 15)) * kRowBytes + (lane >> 4) * 16);
    const uint32_t bRowOff = (uint32_t)((wn * 64 + (lane & 7) + ((lane & 16) >> 1)) * kRowBytes
                                        + ((lane >> 3) & 1) * 16);

    load_chunk(sb, 0, tid, A, B, m0, n0, 0);
    cp_commit();

    const int nChunks = kC / 64;   // 16
    for (int c = 0; c < nChunks; c++) {
        if (c + 1 < nChunks) {
            load_chunk(sb, (c + 1) & 1, tid, A, B, m0, n0, (c + 1) * 64);
            cp_commit();
            cp_wait<1>();
        } else {
            cp_wait<0>();
        }
        __syncthreads();

        const uint32_t st = sb + (c & 1) * kStageBytes;
#pragma unroll
        for (int kk = 0; kk < 4; kk++) {
            const uint32_t kOff = kk * 32;
            uint32_t ah[4][4], b[8][2];
#pragma unroll
            for (int mt = 0; mt < 4; mt++)
                ldsm_x4(ah[mt], st + OFF_A + aRowOff + mt * 16 * kRowBytes + kOff);
#pragma unroll
            for (int np = 0; np < 4; np++)
                ldsm_x4(&b[np * 2][0], st + OFF_B + bRowOff + np * 16 * kRowBytes + kOff);
#pragma unroll
            for (int mt = 0; mt < 4; mt++)
#pragma unroll
                for (int nt = 0; nt < 8; nt++)
                    mma16816(acc[mt][nt], ah[mt], b[nt]);
        }
        __syncthreads();
    }

    const int mBase = m0 + wm * 64;
    const int nBase = n0 + wn * 64;
#pragma unroll
    for (int mt = 0; mt < 4; mt++) {
#pragma unroll
        for (int nt = 0; nt < 8; nt++) {
            float* a4 = acc[mt][nt];
            if (SIG) {
#pragma unroll
                for (int i = 0; i < 4; i++)
                    a4[i] = 1.f / (1.f + __expf(-a4[i]));
            }
            const int r0 = mBase + mt * 16 + (lane >> 2);
            const int cc = nBase + nt * 8 + (lane & 3) * 2;
            if constexpr (sizeof(OutT) == 4) {
                *(float2*)((float*)out + (size_t)r0 * kC + cc)       = make_float2(a4[0], a4[1]);
                *(float2*)((float*)out + (size_t)(r0 + 8) * kC + cc) = make_float2(a4[2], a4[3]);
            } else {
                *(__half2*)((__half*)out + (size_t)r0 * kC + cc)       = __floats2half2_rn(a4[0], a4[1]);
                *(__half2*)((__half*)out + (size_t)(r0 + 8) * kC + cc) = __floats2half2_rn(a4[2], a4[3]);
            }
        }
    }
}

// merged k/v/r GEMM: z=0 -> key(fp32), z=1 -> value(fp16), z=2 -> sigmoid r
__global__ __launch_bounds__(128, 2) void gemm_kvr_kernel() {
    const int m0 = blockIdx.y * 128, n0 = blockIdx.x * 128;
    if (blockIdx.z == 0)      gemm_body<float,  false>(g_a[0], g_w[0], g_k,   m0, n0);
    else if (blockIdx.z == 1) gemm_body<__half, false>(g_a[1], g_w[1], g_v16, m0, n0);
    else                      gemm_body<__half, true >(g_a[2], g_w[2], g_r16, m0, n0);
}
__global__ __launch_bounds__(128, 2) void gemm_out_kernel(float* __restrict__ out) {
    gemm_body<float, false>(g_rw, g_w[3], out, blockIdx.y * 128, blockIdx.x * 128);
}

// ---------------------------------------------------------------------------
// wkv blocked scan (one-exp formulation)
// ---------------------------------------------------------------------------
__global__ void wkv_segA(const float* __restrict__ td) {
    const int c  = blockIdx.x * blockDim.x + threadIdx.x;
    const int bs = blockIdx.y;                 // b*kSeg + seg
    const int b  = bs >> 4;
    const int sg = bs & (kSeg - 1);

    const float w = -__expf(td[c]);
    const size_t base = ((size_t)b * kT + (size_t)sg * kSegLen) * kC + c;
    const float*  kp = g_k   + base;
    const __half* vp = g_v16 + base;

    float num = 0.f, den = 0.f, mx = -1e38f;
#pragma unroll 4
    for (int i = 0; i < kSegLen; i++) {
        const float k = kp[(size_t)i * kC];
        const float v = __half2float(vp[(size_t)i * kC]);
        const float mw = mx + w;
        const float d  = mw - k;
        const bool  p  = d >= 0.f;
        const float e  = __expf(p ? -d : d);
        const float f1 = p ? 1.f : e;
        const float f2 = p ? e : 1.f;
        num = fmaf(f1, num, f2 * v);
        den = fmaf(f1, den, f2);
        mx  = p ? mw : k;
    }
    const size_t si = (size_t)bs * kC + c;
    g_segN[si] = num;
    g_segD[si] = den;
    g_segM[si] = mx;
}

__global__ void wkv_prefix(const float* __restrict__ td) {
    const int idx = blockIdx.x * blockDim.x + threadIdx.x;
    const int b = idx >> 10;
    const int c = idx & (kC - 1);
    const float w = -__expf(td[c]);
    const float shift = (float)kSegLen * w;

    float n[kSeg], d[kSeg], m[kSeg];
#pragma unroll
    for (int s = 0; s < kSeg; s++) {
        const size_t si = ((size_t)(b * kSeg + s)) * kC + c;
        n[s] = g_segN[si];
        d[s] = g_segD[si];
        m[s] = g_segM[si];
    }
    float N = 0.f, D = 0.f, M = -1e38f;
#pragma unroll
    for (int s = 0; s < kSeg; s++) {
        const size_t si = ((size_t)(b * kSeg + s)) * kC + c;
        g_segN[si] = N;
        g_segD[si] = D;
        g_segM[si] = M;
        const float Ms = M + shift;
        const float dd = Ms - m[s];
        const bool  p  = dd >= 0.f;
        const float e  = __expf(p ? -dd : dd);
        const float f1 = p ? 1.f : e;
        const float f2 = p ? e : 1.f;
        N = fmaf(f1, N, f2 * n[s]);
        D = fmaf(f1, D, f2 * d[s]);
        M = p ? Ms : m[s];
    }
}

__global__ void wkv_segB(const float* __restrict__ td, const float* __restrict__ tf) {
    const int c  = blockIdx.x * blockDim.x + threadIdx.x;
    const int bs = blockIdx.y;
    const int b  = bs >> 4;
    const int sg = bs & (kSeg - 1);

    const float w = -__expf(td[c]);
    const float u = tf[c];

    const size_t si = (size_t)bs * kC + c;
    float num = g_segN[si];
    float den = g_segD[si];
    float mx  = g_segM[si];

    const size_t base = ((size_t)b * kT + (size_t)sg * kSegLen) * kC + c;
    const float*  kp = g_k   + base;
    const __half* vp = g_v16 + base;
    const __half* rp = g_r16 + base;
    __half* op = g_rw + base;

#pragma unroll 4
    for (int i = 0; i < kSegLen; i++) {
        const size_t o = (size_t)i * kC;
        const float k = kp[o];
        const float v = __half2float(vp[o]);
        const float r = __half2float(rp[o]);
        const float ku  = k + u;
        const float do_ = mx - ku;
        const bool  po  = do_ >= 0.f;
        const float eo  = __expf(po ? -do_ : do_);
        const float g1  = po ? 1.f : eo;
        const float g2  = po ? eo : 1.f;
        const float outv = __fdividef(fmaf(g1, num, g2 * v), fmaf(g1, den, g2));
        const float mw = mx + w;
        const float d  = mw - k;
        const bool  p  = d >= 0.f;
        const float e  = __expf(p ? -d : d);
        const float f1 = p ? 1.f : e;
        const float f2 = p ? e : 1.f;
        num = fmaf(f1, num, f2 * v);
        den = fmaf(f1, den, f2);
        mx  = p ? mw : k;

        op[o] = __float2half_rn(r * outv);
    }
}

// ---------------------------------------------------------------------------
// Launch
// ---------------------------------------------------------------------------
extern "C" void kernel_launch(void* const* d_in, const int* in_sizes, int n_in,
                              void* d_out, int out_size) {
    const float* x  = (const float*)d_in[0];
    const float* wk = (const float*)d_in[1];
    const float* wv = (const float*)d_in[2];
    const float* wr = (const float*)d_in[3];
    const float* wo = (const float*)d_in[4];
    const float* td = (const float*)d_in[5];
    const float* tf = (const float*)d_in[6];
    const float* mk = (const float*)d_in[7];
    const float* mv = (const float*)d_in[8];
    const float* mr = (const float*)d_in[9];
    float* out = (float*)d_out;

    cudaFuncSetAttribute(gemm_kvr_kernel, cudaFuncAttributeMaxDynamicSharedMemorySize, kSmemBytes);
    cudaFuncSetAttribute(gemm_out_kernel, cudaFuncAttributeMaxDynamicSharedMemorySize, kSmemBytes);

    prep_all_kernel<<<4096 + kM, 256>>>(x, wk, wv, wr, wo, mk, mv, mr);
    gemm_kvr_kernel<<<dim3(kC / 128, kM / 128, 3), 128, kSmemBytes>>>();

    dim3 wgrid(kC / 256, kB * kSeg);   // (4, 128)
    wkv_segA<<<wgrid, 256>>>(td);
    wkv_prefix<<<(kB * kC) / 256, 256>>>(td);
    wkv_segB<<<wgrid, 256>>>(td, tf);

    gemm_out_kernel<<<dim3(kC / 128, kM / 128), 128, kSmemBytes>>>(out);
}

// round 14
// speedup vs baseline: 1.1674x; 1.0655x over previous
#include <cuda_runtime.h>
#include <cuda_fp16.h>
#include <cstdint>
#include <math.h>

// Problem shape (fixed): B=8, T=2048, C=1024
constexpr int kB = 8;
constexpr int kT = 2048;
constexpr int kC = 1024;
constexpr int kM = kB * kT;                 // 16384 rows
constexpr size_t kMC = (size_t)kM * kC;
constexpr size_t kCC = (size_t)kC * kC;

constexpr int kSeg    = 16;
constexpr int kSegLen = kT / kSeg;          // 128

// ---------------------------------------------------------------------------
// Scratch (__device__ globals)
// ---------------------------------------------------------------------------
__device__ __half g_a[3][kMC];     // mixed inputs (k,v,r) in fp16
__device__ __half g_w[4][kCC];     // wk,wv,wr,wo in fp16
__device__ __half g_k16[kMC];      // key (fp16)
__device__ __half g_v16[kMC];      // value (fp16)
__device__ __half g_r16[kMC];      // sigmoid(receptance) (fp16)
__device__ __half g_rw[kMC];       // rwkv in fp16
__device__ float g_segN[(size_t)kB * kSeg * kC];
__device__ float g_segD[(size_t)kB * kSeg * kC];
__device__ float g_segM[(size_t)kB * kSeg * kC];

// ---------------------------------------------------------------------------
// PTX helpers
// ---------------------------------------------------------------------------
__device__ __forceinline__ uint32_t smem_u32(const void* p) {
    uint32_t a;
    asm("{ .reg .u64 t; cvta.to.shared.u64 t, %1; cvt.u32.u64 %0, t; }"
        : "=r"(a) : "l"(p));
    return a;
}
__device__ __forceinline__ void cp_async16(uint32_t saddr, const void* gptr) {
    asm volatile("cp.async.ca.shared.global [%0], [%1], 16;"
                 :: "r"(saddr), "l"(gptr));
}
__device__ __forceinline__ void cp_commit() {
    asm volatile("cp.async.commit_group;");
}
template <int N>
__device__ __forceinline__ void cp_wait() {
    asm volatile("cp.async.wait_group %0;" :: "n"(N));
}
__device__ __forceinline__ void ldsm_x4(uint32_t* r, uint32_t addr) {
    asm volatile("ldmatrix.sync.aligned.m8n8.x4.shared.b16 {%0,%1,%2,%3}, [%4];"
                 : "=r"(r[0]), "=r"(r[1]), "=r"(r[2]), "=r"(r[3]) : "r"(addr));
}
__device__ __forceinline__ void mma16816(float* d, const uint32_t* a, const uint32_t* b) {
    asm volatile("mma.sync.aligned.m16n8k16.row.col.f32.f16.f16.f32 "
                 "{%0,%1,%2,%3}, {%4,%5,%6,%7}, {%8,%9}, {%0,%1,%2,%3};"
                 : "+f"(d[0]), "+f"(d[1]), "+f"(d[2]), "+f"(d[3])
                 : "r"(a[0]), "r"(a[1]), "r"(a[2]), "r"(a[3]), "r"(b[0]), "r"(b[1]));
}

__device__ __forceinline__ void h4_store(const float* a, __half* d, size_t off) {
    unsigned short u[4];
#pragma unroll
    for (int i = 0; i < 4; i++) u[i] = __half_as_ushort(__float2half_rn(a[i]));
    *(uint2*)(d + off) = make_uint2((uint32_t)u[0] | ((uint32_t)u[1] << 16),
                                    (uint32_t)u[2] | ((uint32_t)u[3] << 16));
}

// ---------------------------------------------------------------------------
// prep: weights + mixed inputs in ONE launch
// ---------------------------------------------------------------------------
__global__ __launch_bounds__(256) void prep_all_kernel(
    const float* __restrict__ x,
    const float* __restrict__ wk, const float* __restrict__ wv,
    const float* __restrict__ wr, const float* __restrict__ wo,
    const float* __restrict__ mk, const float* __restrict__ mv,
    const float* __restrict__ mr)
{
    const int bid = blockIdx.x;
    const int c4  = threadIdx.x;
    if (bid < 4096) {
        const int mat = bid >> 10;
        const int row = bid & 1023;
        const float* src = mat == 0 ? wk : mat == 1 ? wv : mat == 2 ? wr : wo;
        float4 v = ((const float4*)(src + (size_t)row * kC))[c4];
        h4_store((const float*)&v, g_w[mat], (size_t)row * kC + c4 * 4);
        return;
    }
    const int row = bid - 4096;
    const float4 xv = ((const float4*)(x + (size_t)row * kC))[c4];
    float4 pv = make_float4(0.f, 0.f, 0.f, 0.f);
    if ((row & (kT - 1)) != 0)
        pv = ((const float4*)(x + (size_t)(row - 1) * kC))[c4];
    const float4 m0 = ((const float4*)mk)[c4];
    const float4 m1 = ((const float4*)mv)[c4];
    const float4 m2 = ((const float4*)mr)[c4];
    const float* xe = (const float*)&xv;
    const float* pe = (const float*)&pv;
    const float* me[3] = {(const float*)&m0, (const float*)&m1, (const float*)&m2};
    const size_t off = (size_t)row * kC + c4 * 4;
#pragma unroll
    for (int s = 0; s < 3; s++) {
        float a[4];
#pragma unroll
        for (int i = 0; i < 4; i++)
            a[i] = fmaf(me[s][i], xe[i] - pe[i], pe[i]);
        h4_store(a, g_a[s], off);
    }
}

// ---------------------------------------------------------------------------
// fp16 warp-MMA GEMM: CTA 128x128, 4 warps, warp tile 64x64, K-chunk 64
// ---------------------------------------------------------------------------
constexpr int kStrideB16 = 72;
constexpr int kRowBytes  = kStrideB16 * 2;   // 144
constexpr int kTileBytes = 128 * kRowBytes;  // 18432
constexpr int kStageBytes = 2 * kTileBytes;  // 36864
constexpr int kSmemBytes  = 2 * kStageBytes; // 73728
constexpr int OFF_A = 0;
constexpr int OFF_B = kTileBytes;

__device__ __forceinline__ void load_chunk(uint32_t sb, int stage, int tid,
                                           const __half* A, const __half* B,
                                           int m0, int n0, int k0) {
    const uint32_t st = sb + stage * kStageBytes;
    const __half* srcs[2] = {A, B};
    const int bases[2] = {m0, n0};
    const uint32_t offs[2] = {OFF_A, OFF_B};
#pragma unroll
    for (int t = 0; t < 2; t++) {
#pragma unroll
        for (int rep = 0; rep < 8; rep++) {
            const int j = tid + rep * 128;
            const int row = j >> 3;
            const int seg = j & 7;
            const __half* g = srcs[t] + (size_t)(bases[t] + row) * kC + k0 + seg * 8;
            cp_async16(st + offs[t] + row * kRowBytes + seg * 16, g);
        }
    }
}

template <typename OutT, bool SIG>
__device__ __forceinline__ void gemm_body(const __half* __restrict__ A,
                                          const __half* __restrict__ B,
                                          OutT* __restrict__ out,
                                          int m0, int n0) {
    extern __shared__ char smem[];
    const uint32_t sb = smem_u32(smem);
    const int tid  = threadIdx.x;
    const int wid  = tid >> 5;
    const int lane = tid & 31;
    const int wm   = wid & 1;
    const int wn   = wid >> 1;

    float acc[4][8][4];
#pragma unroll
    for (int mt = 0; mt < 4; mt++)
#pragma unroll
        for (int nt = 0; nt < 8; nt++)
#pragma unroll
            for (int i = 0; i < 4; i++) acc[mt][nt][i] = 0.f;

    const uint32_t aRowOff = (uint32_t)((wm * 64 + (lane & 15)) * kRowBytes + (lane >> 4) * 16);
    const uint32_t bRowOff = (uint32_t)((wn * 64 + (lane & 7) + ((lane & 16) >> 1)) * kRowBytes
                                        + ((lane >> 3) & 1) * 16);

    load_chunk(sb, 0, tid, A, B, m0, n0, 0);
    cp_commit();

    const int nChunks = kC / 64;   // 16
    for (int c = 0; c < nChunks; c++) {
        if (c + 1 < nChunks) {
            load_chunk(sb, (c + 1) & 1, tid, A, B, m0, n0, (c + 1) * 64);
            cp_commit();
            cp_wait<1>();
        } else {
            cp_wait<0>();
        }
        __syncthreads();

        const uint32_t st = sb + (c & 1) * kStageBytes;
#pragma unroll
        for (int kk = 0; kk < 4; kk++) {
            const uint32_t kOff = kk * 32;
            uint32_t ah[4][4], b[8][2];
#pragma unroll
            for (int mt = 0; mt < 4; mt++)
                ldsm_x4(ah[mt], st + OFF_A + aRowOff + mt * 16 * kRowBytes + kOff);
#pragma unroll
            for (int np = 0; np < 4; np++)
                ldsm_x4(&b[np * 2][0], st + OFF_B + bRowOff + np * 16 * kRowBytes + kOff);
#pragma unroll
            for (int mt = 0; mt < 4; mt++)
#pragma unroll
                for (int nt = 0; nt < 8; nt++)
                    mma16816(acc[mt][nt], ah[mt], b[nt]);
        }
        __syncthreads();
    }

    const int mBase = m0 + wm * 64;
    const int nBase = n0 + wn * 64;
#pragma unroll
    for (int mt = 0; mt < 4; mt++) {
#pragma unroll
        for (int nt = 0; nt < 8; nt++) {
            float* a4 = acc[mt][nt];
            if (SIG) {
#pragma unroll
                for (int i = 0; i < 4; i++)
                    a4[i] = 1.f / (1.f + __expf(-a4[i]));
            }
            const int r0 = mBase + mt * 16 + (lane >> 2);
            const int cc = nBase + nt * 8 + (lane & 3) * 2;
            if constexpr (sizeof(OutT) == 4) {
                *(float2*)((float*)out + (size_t)r0 * kC + cc)       = make_float2(a4[0], a4[1]);
                *(float2*)((float*)out + (size_t)(r0 + 8) * kC + cc) = make_float2(a4[2], a4[3]);
            } else {
                *(__half2*)((__half*)out + (size_t)r0 * kC + cc)       = __floats2half2_rn(a4[0], a4[1]);
                *(__half2*)((__half*)out + (size_t)(r0 + 8) * kC + cc) = __floats2half2_rn(a4[2], a4[3]);
            }
        }
    }
}

// merged k/v/r GEMM
__global__ __launch_bounds__(128, 2) void gemm_kvr_kernel() {
    const int m0 = blockIdx.y * 128, n0 = blockIdx.x * 128;
    if (blockIdx.z == 0)      gemm_body<__half, false>(g_a[0], g_w[0], g_k16, m0, n0);
    else if (blockIdx.z == 1) gemm_body<__half, false>(g_a[1], g_w[1], g_v16, m0, n0);
    else                      gemm_body<__half, true >(g_a[2], g_w[2], g_r16, m0, n0);
}
__global__ __launch_bounds__(128, 2) void gemm_out_kernel(float* __restrict__ out) {
    gemm_body<float, false>(g_rw, g_w[3], out, blockIdx.y * 128, blockIdx.x * 128);
}

// ---------------------------------------------------------------------------
// wkv blocked scan (one-exp formulation, 8-step batched loads for MLP)
// ---------------------------------------------------------------------------
__global__ void wkv_segA(const float* __restrict__ td) {
    const int c  = blockIdx.x * blockDim.x + threadIdx.x;
    const int bs = blockIdx.y;                 // b*kSeg + seg
    const int b  = bs >> 4;
    const int sg = bs & (kSeg - 1);

    const float w = -__expf(td[c]);
    const size_t base = ((size_t)b * kT + (size_t)sg * kSegLen) * kC + c;
    const __half* kp = g_k16 + base;
    const __half* vp = g_v16 + base;

    float num = 0.f, den = 0.f, mx = -1e38f;
    for (int g = 0; g < kSegLen / 8; g++) {
        float kk[8], vv[8];
#pragma unroll
        for (int j = 0; j < 8; j++) {
            const size_t o = (size_t)(g * 8 + j) * kC;
            kk[j] = __half2float(kp[o]);
            vv[j] = __half2float(vp[o]);
        }
#pragma unroll
        for (int j = 0; j < 8; j++) {
            const float mw = mx + w;
            const float d  = mw - kk[j];
            const bool  p  = d >= 0.f;
            const float e  = __expf(p ? -d : d);
            const float f1 = p ? 1.f : e;
            const float f2 = p ? e : 1.f;
            num = fmaf(f1, num, f2 * vv[j]);
            den = fmaf(f1, den, f2);
            mx  = p ? mw : kk[j];
        }
    }
    const size_t si = (size_t)bs * kC + c;
    g_segN[si] = num;
    g_segD[si] = den;
    g_segM[si] = mx;
}

__global__ void wkv_prefix(const float* __restrict__ td) {
    const int idx = blockIdx.x * blockDim.x + threadIdx.x;
    const int b = idx >> 10;
    const int c = idx & (kC - 1);
    const float w = -__expf(td[c]);
    const float shift = (float)kSegLen * w;

    float n[kSeg], d[kSeg], m[kSeg];
#pragma unroll
    for (int s = 0; s < kSeg; s++) {
        const size_t si = ((size_t)(b * kSeg + s)) * kC + c;
        n[s] = g_segN[si];
        d[s] = g_segD[si];
        m[s] = g_segM[si];
    }
    float N = 0.f, D = 0.f, M = -1e38f;
#pragma unroll
    for (int s = 0; s < kSeg; s++) {
        const size_t si = ((size_t)(b * kSeg + s)) * kC + c;
        g_segN[si] = N;
        g_segD[si] = D;
        g_segM[si] = M;
        const float Ms = M + shift;
        const float dd = Ms - m[s];
        const bool  p  = dd >= 0.f;
        const float e  = __expf(p ? -dd : dd);
        const float f1 = p ? 1.f : e;
        const float f2 = p ? e : 1.f;
        N = fmaf(f1, N, f2 * n[s]);
        D = fmaf(f1, D, f2 * d[s]);
        M = p ? Ms : m[s];
    }
}

__global__ void wkv_segB(const float* __restrict__ td, const float* __restrict__ tf) {
    const int c  = blockIdx.x * blockDim.x + threadIdx.x;
    const int bs = blockIdx.y;
    const int b  = bs >> 4;
    const int sg = bs & (kSeg - 1);

    const float w = -__expf(td[c]);
    const float u = tf[c];

    const size_t si = (size_t)bs * kC + c;
    float num = g_segN[si];
    float den = g_segD[si];
    float mx  = g_segM[si];

    const size_t base = ((size_t)b * kT + (size_t)sg * kSegLen) * kC + c;
    const __half* kp = g_k16 + base;
    const __half* vp = g_v16 + base;
    const __half* rp = g_r16 + base;
    __half* op = g_rw + base;

    for (int g = 0; g < kSegLen / 8; g++) {
        float kk[8], vv[8], rr[8];
#pragma unroll
        for (int j = 0; j < 8; j++) {
            const size_t o = (size_t)(g * 8 + j) * kC;
            kk[j] = __half2float(kp[o]);
            vv[j] = __half2float(vp[o]);
            rr[j] = __half2float(rp[o]);
        }
        __half ov[8];
#pragma unroll
        for (int j = 0; j < 8; j++) {
            const float ku  = kk[j] + u;
            const float do_ = mx - ku;
            const bool  po  = do_ >= 0.f;
            const float eo  = __expf(po ? -do_ : do_);
            const float g1  = po ? 1.f : eo;
            const float g2  = po ? eo : 1.f;
            const float outv = __fdividef(fmaf(g1, num, g2 * vv[j]), fmaf(g1, den, g2));
            const float mw = mx + w;
            const float d  = mw - kk[j];
            const bool  p  = d >= 0.f;
            const float e  = __expf(p ? -d : d);
            const float f1 = p ? 1.f : e;
            const float f2 = p ? e : 1.f;
            num = fmaf(f1, num, f2 * vv[j]);
            den = fmaf(f1, den, f2);
            mx  = p ? mw : kk[j];
            ov[j] = __float2half_rn(rr[j] * outv);
        }
#pragma unroll
        for (int j = 0; j < 8; j++)
            op[(size_t)(g * 8 + j) * kC] = ov[j];
    }
}

// ---------------------------------------------------------------------------
// Launch
// ---------------------------------------------------------------------------
extern "C" void kernel_launch(void* const* d_in, const int* in_sizes, int n_in,
                              void* d_out, int out_size) {
    const float* x  = (const float*)d_in[0];
    const float* wk = (const float*)d_in[1];
    const float* wv = (const float*)d_in[2];
    const float* wr = (const float*)d_in[3];
    const float* wo = (const float*)d_in[4];
    const float* td = (const float*)d_in[5];
    const float* tf = (const float*)d_in[6];
    const float* mk = (const float*)d_in[7];
    const float* mv = (const float*)d_in[8];
    const float* mr = (const float*)d_in[9];
    float* out = (float*)d_out;

    cudaFuncSetAttribute(gemm_kvr_kernel, cudaFuncAttributeMaxDynamicSharedMemorySize, kSmemBytes);
    cudaFuncSetAttribute(gemm_out_kernel, cudaFuncAttributeMaxDynamicSharedMemorySize, kSmemBytes);

    prep_all_kernel<<<4096 + kM, 256>>>(x, wk, wv, wr, wo, mk, mv, mr);
    gemm_kvr_kernel<<<dim3(kC / 128, kM / 128, 3), 128, kSmemBytes>>>();

    dim3 wgrid(kC / 256, kB * kSeg);   // (4, 128)
    wkv_segA<<<wgrid, 256>>>(td);
    wkv_prefix<<<(kB * kC) / 256, 256>>>(td);
    wkv_segB<<<wgrid, 256>>>(td, tf);

    gemm_out_kernel<<<dim3(kC / 128, kM / 128), 128, kSmemBytes>>>(out);
}